// round 1
// baseline (speedup 1.0000x reference)
#include <cuda_runtime.h>

#define N_GAUSS 3200
#define FEAT    17
#define RH      48
#define RW      88
#define NPIX    (RH*RW)       // 4224 = 33*128
#define NCAM    2
#define GH      192
#define GW      352
#define NSEG    25
#define SEGSZ   128           // 25*128 = 3200
#define KCH     4
#define KLEN    (N_GAUSS/KCH) // 800
#define NTILES  (NPIX/128)    // 33

// -------- device scratch (static: allocation-free) --------
__device__ float d_z  [NCAM*N_GAUSS];
__device__ float d_tu [NCAM*N_GAUSS];
__device__ float d_tv [NCAM*N_GAUSS];
__device__ float d_tA [NCAM*N_GAUSS];
__device__ float d_tB [NCAM*N_GAUSS];
__device__ float d_tC [NCAM*N_GAUSS];
__device__ float d_top[NCAM*N_GAUSS];
__device__ int   d_rank[NCAM*N_GAUSS];
__device__ float d_su [NCAM*N_GAUSS];
__device__ float d_sv [NCAM*N_GAUSS];
__device__ float d_sA [NCAM*N_GAUSS];
__device__ float d_sB [NCAM*N_GAUSS];
__device__ float d_sC [NCAM*N_GAUSS];
__device__ float d_sop[NCAM*N_GAUSS];
__device__ float d_sf [NCAM*N_GAUSS*FEAT];
__device__ float d_segT[NCAM*NSEG*NPIX];
__device__ float d_segA[NCAM*NSEG*FEAT*NPIX];
__device__ float d_num[NCAM];
__device__ float d_den[NCAM];

// -------- 1) per-gaussian projection + cov2d inverse --------
__global__ void k_pre(const float* __restrict__ xyz, const float* __restrict__ scales,
                      const float* __restrict__ rots, const float* __restrict__ opac,
                      const float* __restrict__ vm, const float* __restrict__ intr)
{
    int n   = blockIdx.x * blockDim.x + threadIdx.x;
    int cam = blockIdx.y;
    if (cam == 0 && blockIdx.x == 0 && threadIdx.x < NCAM) {
        d_num[threadIdx.x] = 0.f; d_den[threadIdx.x] = 0.f;
    }
    if (n >= N_GAUSS) return;
    d_rank[cam*N_GAUSS + n] = 0;

    const float* V = vm + cam*16;
    float fx = intr[cam*4+0], fy = intr[cam*4+1], cx = intr[cam*4+2], cy = intr[cam*4+3];
    float X = xyz[3*n], Y = xyz[3*n+1], Z = xyz[3*n+2];
    float p0 = V[0]*X + V[1]*Y + V[2] *Z + V[3];
    float p1 = V[4]*X + V[5]*Y + V[6] *Z + V[7];
    float p2 = V[8]*X + V[9]*Y + V[10]*Z + V[11];
    float z  = p2;
    float zc = fmaxf(z, 0.2f);
    float iz = 1.0f / zc;
    float u  = fx*p0*iz + cx;
    float v  = fy*p1*iz + cy;

    // quaternion -> rotation
    float qw = rots[4*n], qx = rots[4*n+1], qy = rots[4*n+2], qz = rots[4*n+3];
    float qn = rsqrtf(qw*qw + qx*qx + qy*qy + qz*qz);
    qw *= qn; qx *= qn; qy *= qn; qz *= qn;
    float R00 = 1.f-2.f*(qy*qy+qz*qz), R01 = 2.f*(qx*qy-qw*qz), R02 = 2.f*(qx*qz+qw*qy);
    float R10 = 2.f*(qx*qy+qw*qz),     R11 = 1.f-2.f*(qx*qx+qz*qz), R12 = 2.f*(qy*qz-qw*qx);
    float R20 = 2.f*(qx*qz-qw*qy),     R21 = 2.f*(qy*qz+qw*qx), R22 = 1.f-2.f*(qx*qx+qy*qy);

    float s0 = __expf(scales[3*n]), s1 = __expf(scales[3*n+1]), s2 = __expf(scales[3*n+2]);
    float e0 = s0*s0, e1 = s1*s1, e2 = s2*s2;

    // M = R diag(e) R^T (symmetric)
    float M00 = R00*R00*e0 + R01*R01*e1 + R02*R02*e2;
    float M01 = R00*R10*e0 + R01*R11*e1 + R02*R12*e2;
    float M02 = R00*R20*e0 + R01*R21*e1 + R02*R22*e2;
    float M11 = R10*R10*e0 + R11*R11*e1 + R12*R12*e2;
    float M12 = R10*R20*e0 + R11*R21*e1 + R12*R22*e2;
    float M22 = R20*R20*e0 + R21*R21*e1 + R22*R22*e2;

    float W00=V[0],W01=V[1],W02=V[2];
    float W10=V[4],W11=V[5],W12=V[6];
    float W20=V[8],W21=V[9],W22=V[10];
    // Tmp = W * M
    float T00=W00*M00+W01*M01+W02*M02, T01=W00*M01+W01*M11+W02*M12, T02=W00*M02+W01*M12+W02*M22;
    float T10=W10*M00+W11*M01+W12*M02, T11=W10*M01+W11*M11+W12*M12, T12=W10*M02+W11*M12+W12*M22;
    float T20=W20*M00+W21*M01+W22*M02, T21=W20*M01+W21*M11+W22*M12, T22=W20*M02+W21*M12+W22*M22;
    // Ccov = Tmp * W^T (symmetric)
    float C00=T00*W00+T01*W01+T02*W02;
    float C01=T00*W10+T01*W11+T02*W12;
    float C02=T00*W20+T01*W21+T02*W22;
    float C11=T10*W10+T11*W11+T12*W12;
    float C12=T10*W20+T11*W21+T12*W22;
    float C22=T20*W20+T21*W21+T22*W22;

    // J cov J^T with J = [[fx/zc,0,-fx p0/zc^2],[0,fy/zc,-fy p1/zc^2]]
    float fz0 = fx*iz, fz1 = fy*iz;
    float g0 = -fx*p0*iz*iz, g1 = -fy*p1*iz*iz;
    float t0x = C00*fz0 + C02*g0;
    float t0y = C01*fz0 + C12*g0;
    float t0z = C02*fz0 + C22*g0;
    float cov00 = fz0*t0x + g0*t0z;
    float cov01 = fz1*t0y + g1*t0z;
    float t1y = C11*fz1 + C12*g1;
    float t1z = C12*fz1 + C22*g1;
    float cov11 = fz1*t1y + g1*t1z;

    float a = cov00 + 0.3f;
    float b = cov01;
    float c = cov11 + 0.3f;
    float det  = fmaxf(a*c - b*b, 1e-8f);
    float idet = 1.0f / det;

    float oz = (z > 0.2f) ? opac[n] : 0.0f;
    int gi = cam*N_GAUSS + n;
    d_z [gi] = z;
    d_tu[gi] = u;   d_tv[gi] = v;
    d_tA[gi] = c*idet; d_tB[gi] = -b*idet; d_tC[gi] = a*idet;
    d_top[gi] = oz;
}

// -------- 2) stable argsort via O(N^2) rank counting (split over KCH chunks) --------
__global__ void k_rank()
{
    int cam = blockIdx.z;
    int n   = blockIdx.x * 256 + threadIdx.x;
    int base = blockIdx.y * KLEN;
    __shared__ float tz[256];
    float zn = (n < N_GAUSS) ? d_z[cam*N_GAUSS + n] : 0.f;
    int cnt = 0;
    for (int t0 = 0; t0 < KLEN; t0 += 256) {
        int lim = KLEN - t0 < 256 ? KLEN - t0 : 256;
        __syncthreads();
        if (threadIdx.x < lim) tz[threadIdx.x] = d_z[cam*N_GAUSS + base + t0 + threadIdx.x];
        __syncthreads();
        if (n < N_GAUSS) {
            for (int j = 0; j < lim; j++) {
                float zm = tz[j];
                int mm = base + t0 + j;
                cnt += (zm < zn) || (zm == zn && mm < n);
            }
        }
    }
    if (n < N_GAUSS && cnt) atomicAdd(&d_rank[cam*N_GAUSS + n], cnt);
}

// -------- 3) scatter params + features into sorted order --------
__global__ void k_scatter(const float* __restrict__ feats)
{
    int n = blockIdx.x * 256 + threadIdx.x;
    int cam = blockIdx.y;
    if (n >= N_GAUSS) return;
    int gi  = cam*N_GAUSS + n;
    int pos = cam*N_GAUSS + d_rank[gi];
    d_su[pos] = d_tu[gi];  d_sv[pos] = d_tv[gi];
    d_sA[pos] = d_tA[gi];  d_sB[pos] = d_tB[gi];  d_sC[pos] = d_tC[gi];
    d_sop[pos] = d_top[gi];
#pragma unroll
    for (int c = 0; c < FEAT; c++)
        d_sf[pos*FEAT + c] = feats[n*FEAT + c];
}

// -------- 4) segmented alpha compositing --------
__global__ void __launch_bounds__(128) k_render()
{
    int seg  = blockIdx.x;
    int tile = blockIdx.y;
    int cam  = blockIdx.z;
    __shared__ float su[SEGSZ], sv[SEGSZ], sA[SEGSZ], sB[SEGSZ], sC[SEGSZ], sop[SEGSZ];
    __shared__ float sf[SEGSZ*FEAT];
    int t = threadIdx.x;
    int g = cam*N_GAUSS + seg*SEGSZ + t;
    su[t] = d_su[g]; sv[t] = d_sv[g];
    sA[t] = d_sA[g]; sB[t] = d_sB[g]; sC[t] = d_sC[g];
    sop[t] = d_sop[g];
#pragma unroll
    for (int c = 0; c < FEAT; c++) sf[t*FEAT + c] = d_sf[g*FEAT + c];
    __syncthreads();

    int p = tile*128 + t;
    float px = (float)(p % RW);
    float py = (float)(p / RW);
    float T = 1.0f;
    float acc[FEAT];
#pragma unroll
    for (int c = 0; c < FEAT; c++) acc[c] = 0.f;

    for (int i = 0; i < SEGSZ; i++) {
        float dx = px - su[i];
        float dy = py - sv[i];
        float pw = -0.5f*(sA[i]*dx*dx + sC[i]*dy*dy) - sB[i]*dx*dy;
        pw = fminf(pw, 0.0f);
        if (pw > -20.0f) {
            float alpha = fminf(sop[i] * __expf(pw), 0.99f);
            float w = alpha * T;
            const float* fp = &sf[i*FEAT];
#pragma unroll
            for (int c = 0; c < FEAT; c++) acc[c] = fmaf(w, fp[c], acc[c]);
            T *= 1.0f - alpha;
        }
    }
    int idx = cam*NSEG + seg;
    d_segT[idx*NPIX + p] = T;
#pragma unroll
    for (int c = 0; c < FEAT; c++)
        d_segA[(idx*FEAT + c)*NPIX + p] = acc[c];
}

// -------- 5) combine segments (prefix transmittance) + masked weighted CE --------
__global__ void __launch_bounds__(128) k_loss(const int* __restrict__ gt, const int* __restrict__ mk,
                                              const float* __restrict__ cw)
{
    int cam = blockIdx.y;
    int p = blockIdx.x*128 + threadIdx.x;
    float T = 1.0f;
    float logits[FEAT];
#pragma unroll
    for (int c = 0; c < FEAT; c++) logits[c] = 0.f;
    for (int s = 0; s < NSEG; s++) {
        int idx = cam*NSEG + s;
#pragma unroll
        for (int c = 0; c < FEAT; c++)
            logits[c] = fmaf(T, d_segA[(idx*FEAT + c)*NPIX + p], logits[c]);
        T *= d_segT[idx*NPIX + p];
    }
    int x = p % RW, y = p / RW;
    int gi = cam*GH*GW + (y*4)*GW + (x*4);
    int g = gt[gi];
    float m = (float)mk[gi];

    float mx = logits[0];
#pragma unroll
    for (int c = 1; c < FEAT; c++) mx = fmaxf(mx, logits[c]);
    float se = 0.f;
#pragma unroll
    for (int c = 0; c < FEAT; c++) se += __expf(logits[c] - mx);
    float lg = logits[0];
#pragma unroll
    for (int c = 1; c < FEAT; c++) if (c == g) lg = logits[c];
    float nll = -(lg - mx - __logf(se));
    float wi  = cw[g] * m;

    __shared__ float rn[128], rd[128];
    int t = threadIdx.x;
    rn[t] = wi * nll; rd[t] = wi;
    __syncthreads();
    for (int s = 64; s > 0; s >>= 1) {
        if (t < s) { rn[t] += rn[t+s]; rd[t] += rd[t+s]; }
        __syncthreads();
    }
    if (t == 0) {
        atomicAdd(&d_num[cam], rn[0]);
        atomicAdd(&d_den[cam], rd[0]);
    }
}

// -------- 6) finalize --------
__global__ void k_fin(float* out)
{
    float l0 = d_num[0] / fmaxf(d_den[0], 1e-8f);
    float l1 = d_num[1] / fmaxf(d_den[1], 1e-8f);
    out[0] = 0.5f * (l0 + l1);
}

extern "C" void kernel_launch(void* const* d_in, const int* in_sizes, int n_in,
                              void* d_out, int out_size)
{
    const float* vf  = (const float*)d_in[0];  // voxel_feats (1,3200,17)
    const float* op  = (const float*)d_in[1];  // opacity (1,3200,1)
    const float* xyz = (const float*)d_in[2];  // pc_xyz (3200,3)
    const float* sc  = (const float*)d_in[3];  // scales (3200,3)
    const float* rt  = (const float*)d_in[4];  // rots (3200,4)
    const float* vm  = (const float*)d_in[5];  // viewmats (2,4,4)
    const float* in_ = (const float*)d_in[6];  // intrinsics (2,4)
    const float* cw  = (const float*)d_in[7];  // class_weights (17,)
    const int*   gt  = (const int*)  d_in[8];  // gt_sem (2,192,352)
    const int*   mk  = (const int*)  d_in[9];  // sem_mask (2,192,352)
    float* out = (float*)d_out;

    k_pre    <<<dim3(13, NCAM), 256>>>(xyz, sc, rt, op, vm, in_);
    k_rank   <<<dim3(13, KCH, NCAM), 256>>>();
    k_scatter<<<dim3(13, NCAM), 256>>>(vf);
    k_render <<<dim3(NSEG, NTILES, NCAM), 128>>>();
    k_loss   <<<dim3(NTILES, NCAM), 128>>>(gt, mk, cw);
    k_fin    <<<1, 1>>>(out);
}

// round 4
// speedup vs baseline: 1.2499x; 1.2499x over previous
#include <cuda_runtime.h>

#define N_GAUSS 3200
#define FEAT    17
#define FV4     5             // padded feature float4 count (20 floats)
#define RH      48
#define RW      88
#define NPIX    (RH*RW)       // 4224 = 33*128
#define NCAM    2
#define GH      192
#define GW      352
#define NSEG    25
#define SEGSZ   128           // 25*128 = 3200
#define KCH     4
#define KLEN    (N_GAUSS/KCH) // 800
#define NTILES  (NPIX/128)    // 33

// -------- device scratch (static: allocation-free) --------
__device__ float  d_z  [NCAM*N_GAUSS];
__device__ int    d_rank[NCAM*N_GAUSS];
__device__ float4 d_tp0[NCAM*N_GAUSS];   // unsorted u,v,A,B
__device__ float2 d_tp1[NCAM*N_GAUSS];   // unsorted C,op
__device__ float4 d_sp0[NCAM*N_GAUSS];   // sorted
__device__ float2 d_sp1[NCAM*N_GAUSS];
__device__ float4 d_sf4[NCAM*NSEG*FV4*SEGSZ]; // sorted feats, seg-blocked
__device__ float  d_segT[NCAM*NSEG*NPIX];
__device__ float  d_segA[NCAM*NSEG*FEAT*NPIX];
__device__ float  d_num[NCAM];
__device__ float  d_den[NCAM];

// -------- 1) per-gaussian projection + cov2d inverse (R1 math, packed layout) --------
__global__ void k_pre(const float* __restrict__ xyz, const float* __restrict__ scales,
                      const float* __restrict__ rots, const float* __restrict__ opac,
                      const float* __restrict__ vm, const float* __restrict__ intr)
{
    int n   = blockIdx.x * blockDim.x + threadIdx.x;
    int cam = blockIdx.y;
    if (cam == 0 && blockIdx.x == 0 && threadIdx.x < NCAM) {
        d_num[threadIdx.x] = 0.f; d_den[threadIdx.x] = 0.f;
    }
    if (n >= N_GAUSS) return;
    d_rank[cam*N_GAUSS + n] = 0;

    const float* V = vm + cam*16;
    float fx = intr[cam*4+0], fy = intr[cam*4+1], cx = intr[cam*4+2], cy = intr[cam*4+3];
    float X = xyz[3*n], Y = xyz[3*n+1], Z = xyz[3*n+2];
    float p0 = V[0]*X + V[1]*Y + V[2] *Z + V[3];
    float p1 = V[4]*X + V[5]*Y + V[6] *Z + V[7];
    float p2 = V[8]*X + V[9]*Y + V[10]*Z + V[11];
    float z  = p2;
    float zc = fmaxf(z, 0.2f);
    float iz = 1.0f / zc;
    float u  = fx*p0*iz + cx;
    float v  = fy*p1*iz + cy;

    float qw = rots[4*n], qx = rots[4*n+1], qy = rots[4*n+2], qz = rots[4*n+3];
    float qn = rsqrtf(qw*qw + qx*qx + qy*qy + qz*qz);
    qw *= qn; qx *= qn; qy *= qn; qz *= qn;
    float R00 = 1.f-2.f*(qy*qy+qz*qz), R01 = 2.f*(qx*qy-qw*qz), R02 = 2.f*(qx*qz+qw*qy);
    float R10 = 2.f*(qx*qy+qw*qz),     R11 = 1.f-2.f*(qx*qx+qz*qz), R12 = 2.f*(qy*qz-qw*qx);
    float R20 = 2.f*(qx*qz-qw*qy),     R21 = 2.f*(qy*qz+qw*qx), R22 = 1.f-2.f*(qx*qx+qy*qy);

    float s0 = __expf(scales[3*n]), s1 = __expf(scales[3*n+1]), s2 = __expf(scales[3*n+2]);
    float e0 = s0*s0, e1 = s1*s1, e2 = s2*s2;

    float M00 = R00*R00*e0 + R01*R01*e1 + R02*R02*e2;
    float M01 = R00*R10*e0 + R01*R11*e1 + R02*R12*e2;
    float M02 = R00*R20*e0 + R01*R21*e1 + R02*R22*e2;
    float M11 = R10*R10*e0 + R11*R11*e1 + R12*R12*e2;
    float M12 = R10*R20*e0 + R11*R21*e1 + R12*R22*e2;
    float M22 = R20*R20*e0 + R21*R21*e1 + R22*R22*e2;

    float W00=V[0],W01=V[1],W02=V[2];
    float W10=V[4],W11=V[5],W12=V[6];
    float W20=V[8],W21=V[9],W22=V[10];
    float T00=W00*M00+W01*M01+W02*M02, T01=W00*M01+W01*M11+W02*M12, T02=W00*M02+W01*M12+W02*M22;
    float T10=W10*M00+W11*M01+W12*M02, T11=W10*M01+W11*M11+W12*M12, T12=W10*M02+W11*M12+W12*M22;
    float T20=W20*M00+W21*M01+W22*M02, T21=W20*M01+W21*M11+W22*M12, T22=W20*M02+W21*M12+W22*M22;
    float C00=T00*W00+T01*W01+T02*W02;
    float C01=T00*W10+T01*W11+T02*W12;
    float C02=T00*W20+T01*W21+T02*W22;
    float C11=T10*W10+T11*W11+T12*W12;
    float C12=T10*W20+T11*W21+T12*W22;
    float C22=T20*W20+T21*W21+T22*W22;

    float fz0 = fx*iz, fz1 = fy*iz;
    float g0 = -fx*p0*iz*iz, g1 = -fy*p1*iz*iz;
    float t0x = C00*fz0 + C02*g0;
    float t0y = C01*fz0 + C12*g0;
    float t0z = C02*fz0 + C22*g0;
    float cov00 = fz0*t0x + g0*t0z;
    float cov01 = fz1*t0y + g1*t0z;
    float t1y = C11*fz1 + C12*g1;
    float t1z = C12*fz1 + C22*g1;
    float cov11 = fz1*t1y + g1*t1z;

    float a = cov00 + 0.3f;
    float b = cov01;
    float c = cov11 + 0.3f;
    float det  = fmaxf(a*c - b*b, 1e-8f);
    float idet = 1.0f / det;

    float oz = (z > 0.2f) ? opac[n] : 0.0f;
    int gi = cam*N_GAUSS + n;
    d_z  [gi] = z;
    d_tp0[gi] = make_float4(u, v, c*idet, -b*idet);   // u, v, A, B (R1 values)
    d_tp1[gi] = make_float2(a*idet, oz);              // C, op
}

// -------- 2) stable argsort via O(N^2) rank counting (R1-identical) --------
__global__ void k_rank()
{
    int cam = blockIdx.z;
    int n   = blockIdx.x * 256 + threadIdx.x;
    int base = blockIdx.y * KLEN;
    __shared__ float tz[256];
    float zn = (n < N_GAUSS) ? d_z[cam*N_GAUSS + n] : 0.f;
    int cnt = 0;
    for (int t0 = 0; t0 < KLEN; t0 += 256) {
        int lim = KLEN - t0 < 256 ? KLEN - t0 : 256;
        __syncthreads();
        if (threadIdx.x < lim) tz[threadIdx.x] = d_z[cam*N_GAUSS + base + t0 + threadIdx.x];
        __syncthreads();
        if (n < N_GAUSS) {
            for (int j = 0; j < lim; j++) {
                float zm = tz[j];
                int mm = base + t0 + j;
                cnt += (zm < zn) || (zm == zn && mm < n);
            }
        }
    }
    if (n < N_GAUSS && cnt) atomicAdd(&d_rank[cam*N_GAUSS + n], cnt);
}

// -------- 3) scatter packed params + seg-blocked features into sorted order --------
__global__ void k_scatter(const float* __restrict__ feats)
{
    int n = blockIdx.x * 256 + threadIdx.x;
    int cam = blockIdx.y;
    if (n >= N_GAUSS) return;
    int gi   = cam*N_GAUSS + n;
    int rank = d_rank[gi];
    int pos  = cam*N_GAUSS + rank;
    d_sp0[pos] = d_tp0[gi];
    d_sp1[pos] = d_tp1[gi];
    int seg = rank / SEGSZ, t = rank % SEGSZ;
    const float* f = feats + n*FEAT;
    float fv[FV4*4];
#pragma unroll
    for (int c = 0; c < FEAT; c++) fv[c] = f[c];
#pragma unroll
    for (int c = FEAT; c < FV4*4; c++) fv[c] = 0.f;
    float4* dst = &d_sf4[((cam*NSEG + seg)*FV4)*SEGSZ + t];
#pragma unroll
    for (int j = 0; j < FV4; j++)
        dst[j*SEGSZ] = make_float4(fv[4*j], fv[4*j+1], fv[4*j+2], fv[4*j+3]);
}

// -------- 4) segmented alpha compositing (vectorized smem, R1 math) --------
__global__ void __launch_bounds__(128) k_render()
{
    int seg  = blockIdx.x;
    int tile = blockIdx.y;
    int cam  = blockIdx.z;
    __shared__ float4 sp0[SEGSZ];
    __shared__ float2 sp1[SEGSZ];
    __shared__ float4 sf4[FV4*SEGSZ];
    int t = threadIdx.x;
    int g = cam*N_GAUSS + seg*SEGSZ + t;
    sp0[t] = d_sp0[g];
    sp1[t] = d_sp1[g];
    const float4* src = &d_sf4[((cam*NSEG + seg)*FV4)*SEGSZ + t];
#pragma unroll
    for (int j = 0; j < FV4; j++) sf4[j*SEGSZ + t] = src[j*SEGSZ];
    __syncthreads();

    int p = tile*128 + t;
    float px = (float)(p % RW);
    float py = (float)(p / RW);
    float T = 1.0f;
    float acc[FEAT];
#pragma unroll
    for (int c = 0; c < FEAT; c++) acc[c] = 0.f;

    for (int i = 0; i < SEGSZ; i++) {
        float4 P = sp0[i];
        float2 Q = sp1[i];
        float dx = px - P.x;
        float dy = py - P.y;
        float pw = -0.5f*(P.z*dx*dx + Q.x*dy*dy) - P.w*dx*dy;   // exact R1 expression
        pw = fminf(pw, 0.0f);
        if (pw > -20.0f) {
            float alpha = fminf(Q.y * __expf(pw), 0.99f);
            float w = alpha * T;
            float4 f0 = sf4[0*SEGSZ + i];
            float4 f1 = sf4[1*SEGSZ + i];
            float4 f2 = sf4[2*SEGSZ + i];
            float4 f3 = sf4[3*SEGSZ + i];
            float4 f4 = sf4[4*SEGSZ + i];
            acc[0]  = fmaf(w, f0.x, acc[0]);  acc[1]  = fmaf(w, f0.y, acc[1]);
            acc[2]  = fmaf(w, f0.z, acc[2]);  acc[3]  = fmaf(w, f0.w, acc[3]);
            acc[4]  = fmaf(w, f1.x, acc[4]);  acc[5]  = fmaf(w, f1.y, acc[5]);
            acc[6]  = fmaf(w, f1.z, acc[6]);  acc[7]  = fmaf(w, f1.w, acc[7]);
            acc[8]  = fmaf(w, f2.x, acc[8]);  acc[9]  = fmaf(w, f2.y, acc[9]);
            acc[10] = fmaf(w, f2.z, acc[10]); acc[11] = fmaf(w, f2.w, acc[11]);
            acc[12] = fmaf(w, f3.x, acc[12]); acc[13] = fmaf(w, f3.y, acc[13]);
            acc[14] = fmaf(w, f3.z, acc[14]); acc[15] = fmaf(w, f3.w, acc[15]);
            acc[16] = fmaf(w, f4.x, acc[16]);
            T *= 1.0f - alpha;
        }
    }
    int idx = cam*NSEG + seg;
    d_segT[idx*NPIX + p] = T;
#pragma unroll
    for (int c = 0; c < FEAT; c++)
        d_segA[(idx*FEAT + c)*NPIX + p] = acc[c];
}

// -------- 5) combine segments + masked weighted CE (R1-identical) --------
__global__ void __launch_bounds__(128) k_loss(const int* __restrict__ gt, const int* __restrict__ mk,
                                              const float* __restrict__ cw)
{
    int cam = blockIdx.y;
    int p = blockIdx.x*128 + threadIdx.x;
    float T = 1.0f;
    float logits[FEAT];
#pragma unroll
    for (int c = 0; c < FEAT; c++) logits[c] = 0.f;
    for (int s = 0; s < NSEG; s++) {
        int idx = cam*NSEG + s;
#pragma unroll
        for (int c = 0; c < FEAT; c++)
            logits[c] = fmaf(T, d_segA[(idx*FEAT + c)*NPIX + p], logits[c]);
        T *= d_segT[idx*NPIX + p];
    }
    int x = p % RW, y = p / RW;
    int gi = cam*GH*GW + (y*4)*GW + (x*4);
    int g = gt[gi];
    float m = (float)mk[gi];

    float mx = logits[0];
#pragma unroll
    for (int c = 1; c < FEAT; c++) mx = fmaxf(mx, logits[c]);
    float se = 0.f;
#pragma unroll
    for (int c = 0; c < FEAT; c++) se += __expf(logits[c] - mx);
    float lg = logits[0];
#pragma unroll
    for (int c = 1; c < FEAT; c++) if (c == g) lg = logits[c];
    float nll = -(lg - mx - __logf(se));
    float wi  = cw[g] * m;

    __shared__ float rn[128], rd[128];
    int t = threadIdx.x;
    rn[t] = wi * nll; rd[t] = wi;
    __syncthreads();
    for (int s = 64; s > 0; s >>= 1) {
        if (t < s) { rn[t] += rn[t+s]; rd[t] += rd[t+s]; }
        __syncthreads();
    }
    if (t == 0) {
        atomicAdd(&d_num[cam], rn[0]);
        atomicAdd(&d_den[cam], rd[0]);
    }
}

// -------- 6) finalize --------
__global__ void k_fin(float* out)
{
    float l0 = d_num[0] / fmaxf(d_den[0], 1e-8f);
    float l1 = d_num[1] / fmaxf(d_den[1], 1e-8f);
    out[0] = 0.5f * (l0 + l1);
}

extern "C" void kernel_launch(void* const* d_in, const int* in_sizes, int n_in,
                              void* d_out, int out_size)
{
    const float* vf  = (const float*)d_in[0];
    const float* op  = (const float*)d_in[1];
    const float* xyz = (const float*)d_in[2];
    const float* sc  = (const float*)d_in[3];
    const float* rt  = (const float*)d_in[4];
    const float* vm  = (const float*)d_in[5];
    const float* in_ = (const float*)d_in[6];
    const float* cw  = (const float*)d_in[7];
    const int*   gt  = (const int*)  d_in[8];
    const int*   mk  = (const int*)  d_in[9];
    float* out = (float*)d_out;

    k_pre    <<<dim3(13, NCAM), 256>>>(xyz, sc, rt, op, vm, in_);
    k_rank   <<<dim3(13, KCH, NCAM), 256>>>();
    k_scatter<<<dim3(13, NCAM), 256>>>(vf);
    k_render <<<dim3(NSEG, NTILES, NCAM), 128>>>();
    k_loss   <<<dim3(NTILES, NCAM), 128>>>(gt, mk, cw);
    k_fin    <<<1, 1>>>(out);
}